// round 2
// baseline (speedup 1.0000x reference)
#include <cuda_runtime.h>
#include <math.h>

#define NT 8192          // tokens (B*S)
#define ND 1024          // model dim
#define NE 8             // experts
#define NH 2816          // hidden dim
#define NROWS (NT * 2)   // total (token, expert-slot) rows

#define BM 64
#define BN 64
#define BK 16

// ---- device scratch (allocation-free) ----
__device__ int   g_counts[NE];
__device__ int   g_ctr[NE];
__device__ int   g_offsets[NE];
__device__ int   g_route_e[NROWS];
__device__ float g_route_w[NROWS];
__device__ int   g_perm[NROWS];     // row -> token
__device__ float g_pw[NROWS];       // row -> combine weight
__device__ float g_h[(size_t)NROWS * NH];   // SwiGLU activations, 184.5 MB

// ---------------------------------------------------------------------------
// 0) zero output + counters
// ---------------------------------------------------------------------------
__global__ void zero_kernel(float* __restrict__ out) {
    int i = blockIdx.x * blockDim.x + threadIdx.x;
    int n4 = NT * ND / 4;
    if (i < n4) ((float4*)out)[i] = make_float4(0.f, 0.f, 0.f, 0.f);
    if (i < NE) { g_counts[i] = 0; g_ctr[i] = 0; }
}

// ---------------------------------------------------------------------------
// 1) router: logits = x @ gate_w^T, top-2, softmax over the pair
//    one warp per token; gate_w (8x1024 fp32 = 32KB) cached in smem
// ---------------------------------------------------------------------------
__global__ void router_kernel(const float* __restrict__ x,
                              const float* __restrict__ gw) {
    __shared__ float sg[NE * ND];
    int tid = threadIdx.x;
    for (int i = tid; i < NE * ND / 4; i += blockDim.x)
        ((float4*)sg)[i] = ((const float4*)gw)[i];
    __syncthreads();

    int lane = tid & 31;
    int t = blockIdx.x * 8 + (tid >> 5);
    if (t >= NT) return;

    const float4* xv = (const float4*)(x + (size_t)t * ND);
    float acc[NE];
#pragma unroll
    for (int e = 0; e < NE; e++) acc[e] = 0.f;

#pragma unroll
    for (int j = 0; j < ND / 128; j++) {    // 8 float4 per lane
        int v = j * 32 + lane;
        float4 xx = xv[v];
#pragma unroll
        for (int e = 0; e < NE; e++) {
            float4 gg = ((const float4*)sg)[e * (ND / 4) + v];
            acc[e] += xx.x * gg.x + xx.y * gg.y + xx.z * gg.z + xx.w * gg.w;
        }
    }
#pragma unroll
    for (int e = 0; e < NE; e++)
#pragma unroll
        for (int o = 16; o > 0; o >>= 1)
            acc[e] += __shfl_xor_sync(0xffffffffu, acc[e], o);

    if (lane == 0) {
        int b0 = 0;
#pragma unroll
        for (int e = 1; e < NE; e++) if (acc[e] > acc[b0]) b0 = e;
        int b1 = (b0 == 0) ? 1 : 0;
#pragma unroll
        for (int e = 0; e < NE; e++)
            if (e != b0 && acc[e] > acc[b1]) b1 = e;
        // softmax over {l0 >= l1}: w0 = 1/(1+exp(l1-l0))
        float d  = acc[b1] - acc[b0];
        float e1 = expf(d);
        float s  = 1.f + e1;
        g_route_e[2 * t]     = b0;  g_route_w[2 * t]     = 1.f / s;
        g_route_e[2 * t + 1] = b1;  g_route_w[2 * t + 1] = e1 / s;
        atomicAdd(&g_counts[b0], 1);
        atomicAdd(&g_counts[b1], 1);
    }
}

// ---------------------------------------------------------------------------
// 2) exclusive scan over 8 expert counts
// ---------------------------------------------------------------------------
__global__ void scan_kernel() {
    if (threadIdx.x == 0) {
        int o = 0;
        for (int e = 0; e < NE; e++) { g_offsets[e] = o; o += g_counts[e]; }
    }
}

// ---------------------------------------------------------------------------
// 3) scatter (token, slot) pairs into per-expert compacted row lists
// ---------------------------------------------------------------------------
__global__ void scatter_kernel() {
    int i = blockIdx.x * blockDim.x + threadIdx.x;
    if (i >= NROWS) return;
    int e = g_route_e[i];
    int p = atomicAdd(&g_ctr[e], 1);
    int r = g_offsets[e] + p;
    g_perm[r] = i >> 1;
    g_pw[r]   = g_route_w[i];
}

// ---------------------------------------------------------------------------
// 4) GEMM1: gathered X @ {w1^T, w3^T} fused, SiLU-gate epilogue into g_h
//    64x64 tile, K-tile 16, 256 threads, 4x4 (x2 mats) per thread
// ---------------------------------------------------------------------------
__global__ __launch_bounds__(256) void gemm1_kernel(
    const float* __restrict__ x,
    const float* __restrict__ w1,
    const float* __restrict__ w3) {
    int e   = blockIdx.z;
    int cnt = g_counts[e];
    int m0  = blockIdx.y * BM;
    if (m0 >= cnt) return;
    int n0  = blockIdx.x * BN;
    int off = g_offsets[e];

    __shared__ float Xs[BK][BM];
    __shared__ float W1s[BK][BN];
    __shared__ float W3s[BK][BN];
    __shared__ int   stok[BM];

    int tid = threadIdx.x;
    if (tid < BM) {
        int m = m0 + tid;
        stok[tid] = (m < cnt) ? g_perm[off + m] : -1;
    }
    __syncthreads();

    const float* w1e = w1 + (size_t)e * NH * ND;
    const float* w3e = w3 + (size_t)e * NH * ND;

    float acc1[4][4], acc3[4][4];
#pragma unroll
    for (int i = 0; i < 4; i++)
#pragma unroll
        for (int j = 0; j < 4; j++) { acc1[i][j] = 0.f; acc3[i][j] = 0.f; }

    int lr = tid >> 2;            // 0..63 : row within tile (loads)
    int lc = (tid & 3) << 2;      // 0,4,8,12 : k offset (loads)
    int tx = tid & 15, ty = tid >> 4;
    int tok = stok[lr];
    const float4 z4 = make_float4(0.f, 0.f, 0.f, 0.f);

    for (int k0 = 0; k0 < ND; k0 += BK) {
        float4 xv  = (tok >= 0) ? *(const float4*)(x + (size_t)tok * ND + k0 + lc) : z4;
        float4 w1v = *(const float4*)(w1e + (size_t)(n0 + lr) * ND + k0 + lc);
        float4 w3v = *(const float4*)(w3e + (size_t)(n0 + lr) * ND + k0 + lc);
        Xs[lc + 0][lr] = xv.x;  Xs[lc + 1][lr] = xv.y;
        Xs[lc + 2][lr] = xv.z;  Xs[lc + 3][lr] = xv.w;
        W1s[lc + 0][lr] = w1v.x; W1s[lc + 1][lr] = w1v.y;
        W1s[lc + 2][lr] = w1v.z; W1s[lc + 3][lr] = w1v.w;
        W3s[lc + 0][lr] = w3v.x; W3s[lc + 1][lr] = w3v.y;
        W3s[lc + 2][lr] = w3v.z; W3s[lc + 3][lr] = w3v.w;
        __syncthreads();
#pragma unroll
        for (int k = 0; k < BK; k++) {
            float4 a  = *(const float4*)(&Xs[k][ty << 2]);
            float4 b1 = *(const float4*)(&W1s[k][tx << 2]);
            float4 b3 = *(const float4*)(&W3s[k][tx << 2]);
            float av[4]  = {a.x, a.y, a.z, a.w};
            float b1a[4] = {b1.x, b1.y, b1.z, b1.w};
            float b3a[4] = {b3.x, b3.y, b3.z, b3.w};
#pragma unroll
            for (int i = 0; i < 4; i++)
#pragma unroll
                for (int j = 0; j < 4; j++) {
                    acc1[i][j] = fmaf(av[i], b1a[j], acc1[i][j]);
                    acc3[i][j] = fmaf(av[i], b3a[j], acc3[i][j]);
                }
        }
        __syncthreads();
    }

#pragma unroll
    for (int i = 0; i < 4; i++) {
        int m = m0 + (ty << 2) + i;
        if (m >= cnt) break;
        size_t r = (size_t)(off + m);
        float vals[4];
#pragma unroll
        for (int j = 0; j < 4; j++) {
            float a = acc1[i][j];
            float s = a / (1.f + __expf(-a));   // silu
            vals[j] = s * acc3[i][j];
        }
        *(float4*)(g_h + r * NH + n0 + (tx << 2)) =
            make_float4(vals[0], vals[1], vals[2], vals[3]);
    }
}

// ---------------------------------------------------------------------------
// 5) GEMM2: H @ w2^T, scaled by combine weight, atomicAdd into out
// ---------------------------------------------------------------------------
__global__ __launch_bounds__(256) void gemm2_kernel(
    const float* __restrict__ w2, float* __restrict__ out) {
    int e   = blockIdx.z;
    int cnt = g_counts[e];
    int m0  = blockIdx.y * BM;
    if (m0 >= cnt) return;
    int n0  = blockIdx.x * BN;
    int off = g_offsets[e];

    __shared__ float Hs[BK][BM];
    __shared__ float Ws[BK][BN];

    int tid = threadIdx.x;
    const float* w2e = w2 + (size_t)e * ND * NH;

    float acc[4][4];
#pragma unroll
    for (int i = 0; i < 4; i++)
#pragma unroll
        for (int j = 0; j < 4; j++) acc[i][j] = 0.f;

    int lr = tid >> 2;
    int lc = (tid & 3) << 2;
    int tx = tid & 15, ty = tid >> 4;
    bool mvalid = (m0 + lr) < cnt;
    const float* hrow = g_h + (size_t)(off + m0 + lr) * NH;
    const float4 z4 = make_float4(0.f, 0.f, 0.f, 0.f);

    for (int k0 = 0; k0 < NH; k0 += BK) {
        float4 hv = mvalid ? *(const float4*)(hrow + k0 + lc) : z4;
        float4 wv = *(const float4*)(w2e + (size_t)(n0 + lr) * NH + k0 + lc);
        Hs[lc + 0][lr] = hv.x;  Hs[lc + 1][lr] = hv.y;
        Hs[lc + 2][lr] = hv.z;  Hs[lc + 3][lr] = hv.w;
        Ws[lc + 0][lr] = wv.x;  Ws[lc + 1][lr] = wv.y;
        Ws[lc + 2][lr] = wv.z;  Ws[lc + 3][lr] = wv.w;
        __syncthreads();
#pragma unroll
        for (int k = 0; k < BK; k++) {
            float4 a = *(const float4*)(&Hs[k][ty << 2]);
            float4 b = *(const float4*)(&Ws[k][tx << 2]);
            float av[4] = {a.x, a.y, a.z, a.w};
            float bv[4] = {b.x, b.y, b.z, b.w};
#pragma unroll
            for (int i = 0; i < 4; i++)
#pragma unroll
                for (int j = 0; j < 4; j++)
                    acc[i][j] = fmaf(av[i], bv[j], acc[i][j]);
        }
        __syncthreads();
    }

#pragma unroll
    for (int i = 0; i < 4; i++) {
        int m = m0 + (ty << 2) + i;
        if (m >= cnt) break;
        int r = off + m;
        int tok = g_perm[r];
        float w = g_pw[r];
        float* op = out + (size_t)tok * ND + n0 + (tx << 2);
#pragma unroll
        for (int j = 0; j < 4; j++)
            atomicAdd(op + j, w * acc[i][j]);
    }
}

// ---------------------------------------------------------------------------
extern "C" void kernel_launch(void* const* d_in, const int* in_sizes, int n_in,
                              void* d_out, int out_size) {
    const float* x  = (const float*)d_in[0];
    const float* gw = (const float*)d_in[1];
    const float* w1 = (const float*)d_in[2];
    const float* w2 = (const float*)d_in[3];
    const float* w3 = (const float*)d_in[4];
    float* out = (float*)d_out;

    zero_kernel<<<(NT * ND / 4 + 255) / 256, 256>>>(out);
    router_kernel<<<NT / 8, 256>>>(x, gw);
    scan_kernel<<<1, 32>>>();
    scatter_kernel<<<(NROWS + 255) / 256, 256>>>();

    dim3 g1(NH / BN, NT / BM, NE);   // (44, 128, 8) — empty m-tiles exit early
    gemm1_kernel<<<g1, 256>>>(x, w1, w3);

    dim3 g2(ND / BN, NT / BM, NE);   // (16, 128, 8)
    gemm2_kernel<<<g2, 256>>>(w2, out);
}

// round 5
// speedup vs baseline: 3.5408x; 3.5408x over previous
#include <cuda_runtime.h>
#include <math.h>
#include <stdint.h>

#define NT 8192          // tokens (B*S)
#define ND 1024          // model dim
#define NE 8             // experts
#define NH 2816          // hidden dim
#define NROWS (NT * 2)   // total (token, expert-slot) rows

// ---- device scratch (allocation-free) ----
__device__ int   g_counts[NE];
__device__ int   g_ctr[NE];
__device__ int   g_offsets[NE];
__device__ int   g_route_e[NROWS];
__device__ float g_route_w[NROWS];
__device__ int   g_perm[NROWS];     // row -> token
__device__ float g_pw[NROWS];       // row -> combine weight
__device__ float g_h[(size_t)NROWS * NH];   // SwiGLU activations, 184.5 MB

// ---------------------------------------------------------------------------
// tf32 helpers
// ---------------------------------------------------------------------------
__device__ __forceinline__ float tf32r(float f) {
    uint32_t u;
    asm("cvt.rna.tf32.f32 %0, %1;" : "=r"(u) : "f"(f));
    return __uint_as_float(u);
}

__device__ __forceinline__ void mma_tf32(float c[4], const float a[4], const float b[2]) {
    const uint32_t* A = reinterpret_cast<const uint32_t*>(a);
    const uint32_t* B = reinterpret_cast<const uint32_t*>(b);
    asm volatile(
        "mma.sync.aligned.m16n8k8.row.col.f32.tf32.tf32.f32 "
        "{%0,%1,%2,%3},{%4,%5,%6,%7},{%8,%9},{%0,%1,%2,%3};\n"
        : "+f"(c[0]), "+f"(c[1]), "+f"(c[2]), "+f"(c[3])
        : "r"(A[0]), "r"(A[1]), "r"(A[2]), "r"(A[3]), "r"(B[0]), "r"(B[1]));
}

// ---------------------------------------------------------------------------
// 0) zero output + counters
// ---------------------------------------------------------------------------
__global__ void zero_kernel(float* __restrict__ out) {
    int i = blockIdx.x * blockDim.x + threadIdx.x;
    int n4 = NT * ND / 4;
    if (i < n4) ((float4*)out)[i] = make_float4(0.f, 0.f, 0.f, 0.f);
    if (i < NE) { g_counts[i] = 0; g_ctr[i] = 0; }
}

// ---------------------------------------------------------------------------
// 1) router: logits = x @ gate_w^T, top-2, softmax over the pair (exact fp32)
// ---------------------------------------------------------------------------
__global__ void router_kernel(const float* __restrict__ x,
                              const float* __restrict__ gw) {
    __shared__ float sg[NE * ND];
    int tid = threadIdx.x;
    for (int i = tid; i < NE * ND / 4; i += blockDim.x)
        ((float4*)sg)[i] = ((const float4*)gw)[i];
    __syncthreads();

    int lane = tid & 31;
    int t = blockIdx.x * 8 + (tid >> 5);
    if (t >= NT) return;

    const float4* xv = (const float4*)(x + (size_t)t * ND);
    float acc[NE];
#pragma unroll
    for (int e = 0; e < NE; e++) acc[e] = 0.f;

#pragma unroll
    for (int j = 0; j < ND / 128; j++) {
        int v = j * 32 + lane;
        float4 xx = xv[v];
#pragma unroll
        for (int e = 0; e < NE; e++) {
            float4 gg = ((const float4*)sg)[e * (ND / 4) + v];
            acc[e] += xx.x * gg.x + xx.y * gg.y + xx.z * gg.z + xx.w * gg.w;
        }
    }
#pragma unroll
    for (int e = 0; e < NE; e++)
#pragma unroll
        for (int o = 16; o > 0; o >>= 1)
            acc[e] += __shfl_xor_sync(0xffffffffu, acc[e], o);

    if (lane == 0) {
        int b0 = 0;
#pragma unroll
        for (int e = 1; e < NE; e++) if (acc[e] > acc[b0]) b0 = e;
        int b1 = (b0 == 0) ? 1 : 0;
#pragma unroll
        for (int e = 0; e < NE; e++)
            if (e != b0 && acc[e] > acc[b1]) b1 = e;
        float d  = acc[b1] - acc[b0];
        float e1 = expf(d);
        float s  = 1.f + e1;
        g_route_e[2 * t]     = b0;  g_route_w[2 * t]     = 1.f / s;
        g_route_e[2 * t + 1] = b1;  g_route_w[2 * t + 1] = e1 / s;
        atomicAdd(&g_counts[b0], 1);
        atomicAdd(&g_counts[b1], 1);
    }
}

__global__ void scan_kernel() {
    if (threadIdx.x == 0) {
        int o = 0;
        for (int e = 0; e < NE; e++) { g_offsets[e] = o; o += g_counts[e]; }
    }
}

__global__ void scatter_kernel() {
    int i = blockIdx.x * blockDim.x + threadIdx.x;
    if (i >= NROWS) return;
    int e = g_route_e[i];
    int p = atomicAdd(&g_ctr[e], 1);
    int r = g_offsets[e] + p;
    g_perm[r] = i >> 1;
    g_pw[r]   = g_route_w[i];
}

// ---------------------------------------------------------------------------
// 4) GEMM1 (tf32 HMMA): gathered X @ {w1^T, w3^T}, SiLU-gate -> g_h
//    CTA tile 128 x (64 + 64), BK=32, 256 threads, warps 4(m) x 2(n), 32x32/warp
// ---------------------------------------------------------------------------
#define G1_BM 128
#define G1_BN 64
#define G1_BK 32
#define G1_LDS 36   // padded stride: frag LDS banks = 4g+t, conflict-free

__global__ __launch_bounds__(256) void gemm1_kernel(
    const float* __restrict__ x,
    const float* __restrict__ w1,
    const float* __restrict__ w3) {
    int e   = blockIdx.z;
    int cnt = g_counts[e];
    int m0  = blockIdx.y * G1_BM;
    if (m0 >= cnt) return;
    int n0  = blockIdx.x * G1_BN;
    int off = g_offsets[e];

    __shared__ float As[G1_BM][G1_LDS];
    __shared__ float B1s[G1_BN][G1_LDS];
    __shared__ float B3s[G1_BN][G1_LDS];
    __shared__ int   stok[G1_BM];

    int tid = threadIdx.x;
    if (tid < G1_BM) {
        int m = m0 + tid;
        stok[tid] = (m < cnt) ? g_perm[off + m] : -1;
    }
    __syncthreads();

    const float* w1e = w1 + (size_t)e * NH * ND;
    const float* w3e = w3 + (size_t)e * NH * ND;

    // per-thread load slots
    int lrow = tid >> 3;        // 0..31
    int lc4  = (tid & 7) << 2;  // 0,4,...,28

    const float* aptr[4];
    int arow[4];
#pragma unroll
    for (int i = 0; i < 4; i++) {
        arow[i] = lrow + i * 32;
        int tok = stok[arow[i]];
        aptr[i] = (tok >= 0) ? (x + (size_t)tok * ND + lc4) : nullptr;
    }
    const float* b1ptr[2];
    const float* b3ptr[2];
    int brow[2];
#pragma unroll
    for (int i = 0; i < 2; i++) {
        brow[i] = lrow + i * 32;
        b1ptr[i] = w1e + (size_t)(n0 + brow[i]) * ND + lc4;
        b3ptr[i] = w3e + (size_t)(n0 + brow[i]) * ND + lc4;
    }

    int lane = tid & 31, wid = tid >> 5;
    int wm = wid >> 1, wn = wid & 1;
    int g = lane >> 2, t = lane & 3;

    float acc1[2][4][4], acc3[2][4][4];
#pragma unroll
    for (int mi = 0; mi < 2; mi++)
#pragma unroll
        for (int ni = 0; ni < 4; ni++)
#pragma unroll
            for (int q = 0; q < 4; q++) { acc1[mi][ni][q] = 0.f; acc3[mi][ni][q] = 0.f; }

    const float4 z4 = make_float4(0.f, 0.f, 0.f, 0.f);
    float4 aR[4], b1R[2], b3R[2];
#pragma unroll
    for (int i = 0; i < 4; i++) aR[i] = aptr[i] ? *(const float4*)(aptr[i]) : z4;
#pragma unroll
    for (int i = 0; i < 2; i++) { b1R[i] = *(const float4*)(b1ptr[i]); b3R[i] = *(const float4*)(b3ptr[i]); }

    const int KT = ND / G1_BK;   // 32
    for (int kt = 0; kt < KT; kt++) {
        __syncthreads();
#pragma unroll
        for (int i = 0; i < 4; i++) {
            As[arow[i]][lc4 + 0] = tf32r(aR[i].x);
            As[arow[i]][lc4 + 1] = tf32r(aR[i].y);
            As[arow[i]][lc4 + 2] = tf32r(aR[i].z);
            As[arow[i]][lc4 + 3] = tf32r(aR[i].w);
        }
#pragma unroll
        for (int i = 0; i < 2; i++) {
            B1s[brow[i]][lc4 + 0] = tf32r(b1R[i].x);
            B1s[brow[i]][lc4 + 1] = tf32r(b1R[i].y);
            B1s[brow[i]][lc4 + 2] = tf32r(b1R[i].z);
            B1s[brow[i]][lc4 + 3] = tf32r(b1R[i].w);
            B3s[brow[i]][lc4 + 0] = tf32r(b3R[i].x);
            B3s[brow[i]][lc4 + 1] = tf32r(b3R[i].y);
            B3s[brow[i]][lc4 + 2] = tf32r(b3R[i].z);
            B3s[brow[i]][lc4 + 3] = tf32r(b3R[i].w);
        }
        __syncthreads();

        if (kt + 1 < KT) {
            int ko = (kt + 1) * G1_BK;
#pragma unroll
            for (int i = 0; i < 4; i++) aR[i] = aptr[i] ? *(const float4*)(aptr[i] + ko) : z4;
#pragma unroll
            for (int i = 0; i < 2; i++) { b1R[i] = *(const float4*)(b1ptr[i] + ko); b3R[i] = *(const float4*)(b3ptr[i] + ko); }
        }

#pragma unroll
        for (int k8 = 0; k8 < G1_BK / 8; k8++) {
            int kk = k8 * 8;
            float af[2][4];
#pragma unroll
            for (int mi = 0; mi < 2; mi++) {
                int ar = wm * 32 + mi * 16;
                af[mi][0] = As[ar + g][kk + t];
                af[mi][1] = As[ar + g + 8][kk + t];
                af[mi][2] = As[ar + g][kk + t + 4];
                af[mi][3] = As[ar + g + 8][kk + t + 4];
            }
            float bf1[4][2], bf3[4][2];
#pragma unroll
            for (int ni = 0; ni < 4; ni++) {
                int br = wn * 32 + ni * 8 + g;
                bf1[ni][0] = B1s[br][kk + t];
                bf1[ni][1] = B1s[br][kk + t + 4];
                bf3[ni][0] = B3s[br][kk + t];
                bf3[ni][1] = B3s[br][kk + t + 4];
            }
#pragma unroll
            for (int mi = 0; mi < 2; mi++)
#pragma unroll
                for (int ni = 0; ni < 4; ni++) {
                    mma_tf32(acc1[mi][ni], af[mi], bf1[ni]);
                    mma_tf32(acc3[mi][ni], af[mi], bf3[ni]);
                }
        }
    }

    // epilogue: silu(acc1)*acc3 -> g_h
#pragma unroll
    for (int mi = 0; mi < 2; mi++) {
#pragma unroll
        for (int half = 0; half < 2; half++) {
            int mrow = wm * 32 + mi * 16 + g + half * 8;
            int m = m0 + mrow;
            if (m >= cnt) continue;
            size_t r = (size_t)(off + m);
#pragma unroll
            for (int ni = 0; ni < 4; ni++) {
                float a0 = acc1[mi][ni][half * 2 + 0];
                float a1 = acc1[mi][ni][half * 2 + 1];
                float v0 = (a0 / (1.f + __expf(-a0))) * acc3[mi][ni][half * 2 + 0];
                float v1 = (a1 / (1.f + __expf(-a1))) * acc3[mi][ni][half * 2 + 1];
                int col = n0 + wn * 32 + ni * 8 + 2 * t;
                *(float2*)(g_h + r * NH + col) = make_float2(v0, v1);
            }
        }
    }
}

// ---------------------------------------------------------------------------
// 5) GEMM2 (tf32 HMMA): H @ w2^T, * combine weight, atomicAdd into out
//    CTA tile 128 x 128, BK=32, 256 threads, warps 2(m) x 4(n), 64x32/warp
// ---------------------------------------------------------------------------
#define G2_BM 128
#define G2_BN 128
#define G2_BK 32
#define G2_LDS 36

__global__ __launch_bounds__(256) void gemm2_kernel(
    const float* __restrict__ w2, float* __restrict__ out) {
    int e   = blockIdx.z;
    int cnt = g_counts[e];
    int m0  = blockIdx.y * G2_BM;
    if (m0 >= cnt) return;
    int n0  = blockIdx.x * G2_BN;
    int off = g_offsets[e];

    __shared__ float As[G2_BM][G2_LDS];
    __shared__ float Bs[G2_BN][G2_LDS];

    int tid = threadIdx.x;
    const float* w2e = w2 + (size_t)e * ND * NH;

    int lrow = tid >> 3;
    int lc4  = (tid & 7) << 2;

    const float* aptr[4];
    const float* bptr[4];
    int arow[4];
#pragma unroll
    for (int i = 0; i < 4; i++) {
        arow[i] = lrow + i * 32;
        bool valid = (m0 + arow[i]) < cnt;
        aptr[i] = valid ? (g_h + (size_t)(off + m0 + arow[i]) * NH + lc4) : nullptr;
        bptr[i] = w2e + (size_t)(n0 + arow[i]) * NH + lc4;
    }

    int lane = tid & 31, wid = tid >> 5;
    int wm = wid >> 2, wn = wid & 3;
    int g = lane >> 2, t = lane & 3;

    float acc[4][4][4];
#pragma unroll
    for (int mi = 0; mi < 4; mi++)
#pragma unroll
        for (int ni = 0; ni < 4; ni++)
#pragma unroll
            for (int q = 0; q < 4; q++) acc[mi][ni][q] = 0.f;

    const float4 z4 = make_float4(0.f, 0.f, 0.f, 0.f);
    float4 aR[4], bR[4];
#pragma unroll
    for (int i = 0; i < 4; i++) {
        aR[i] = aptr[i] ? *(const float4*)(aptr[i]) : z4;
        bR[i] = *(const float4*)(bptr[i]);
    }

    const int KT = NH / G2_BK;   // 88
    for (int kt = 0; kt < KT; kt++) {
        __syncthreads();
#pragma unroll
        for (int i = 0; i < 4; i++) {
            As[arow[i]][lc4 + 0] = tf32r(aR[i].x);
            As[arow[i]][lc4 + 1] = tf32r(aR[i].y);
            As[arow[i]][lc4 + 2] = tf32r(aR[i].z);
            As[arow[i]][lc4 + 3] = tf32r(aR[i].w);
            Bs[arow[i]][lc4 + 0] = tf32r(bR[i].x);
            Bs[arow[i]][lc4 + 1] = tf32r(bR[i].y);
            Bs[arow[i]][lc4 + 2] = tf32r(bR[i].z);
            Bs[arow[i]][lc4 + 3] = tf32r(bR[i].w);
        }
        __syncthreads();

        if (kt + 1 < KT) {
            int ko = (kt + 1) * G2_BK;
#pragma unroll
            for (int i = 0; i < 4; i++) {
                aR[i] = aptr[i] ? *(const float4*)(aptr[i] + ko) : z4;
                bR[i] = *(const float4*)(bptr[i] + ko);
            }
        }

#pragma unroll
        for (int k8 = 0; k8 < G2_BK / 8; k8++) {
            int kk = k8 * 8;
            float af[4][4];
#pragma unroll
            for (int mi = 0; mi < 4; mi++) {
                int ar = wm * 64 + mi * 16;
                af[mi][0] = As[ar + g][kk + t];
                af[mi][1] = As[ar + g + 8][kk + t];
                af[mi][2] = As[ar + g][kk + t + 4];
                af[mi][3] = As[ar + g + 8][kk + t + 4];
            }
            float bf[4][2];
#pragma unroll
            for (int ni = 0; ni < 4; ni++) {
                int br = wn * 32 + ni * 8 + g;
                bf[ni][0] = Bs[br][kk + t];
                bf[ni][1] = Bs[br][kk + t + 4];
            }
#pragma unroll
            for (int mi = 0; mi < 4; mi++)
#pragma unroll
                for (int ni = 0; ni < 4; ni++)
                    mma_tf32(acc[mi][ni], af[mi], bf[ni]);
        }
    }

    // epilogue: scale by combine weight, atomicAdd into out
#pragma unroll
    for (int mi = 0; mi < 4; mi++) {
#pragma unroll
        for (int half = 0; half < 2; half++) {
            int mrow = wm * 64 + mi * 16 + g + half * 8;
            int m = m0 + mrow;
            if (m >= cnt) continue;
            int r = off + m;
            int tok = g_perm[r];
            float w = g_pw[r];
            float* orow = out + (size_t)tok * ND;
#pragma unroll
            for (int ni = 0; ni < 4; ni++) {
                int col = n0 + wn * 32 + ni * 8 + 2 * t;
                atomicAdd(orow + col,     w * acc[mi][ni][half * 2 + 0]);
                atomicAdd(orow + col + 1, w * acc[mi][ni][half * 2 + 1]);
            }
        }
    }
}

// ---------------------------------------------------------------------------
extern "C" void kernel_launch(void* const* d_in, const int* in_sizes, int n_in,
                              void* d_out, int out_size) {
    const float* x  = (const float*)d_in[0];
    const float* gw = (const float*)d_in[1];
    const float* w1 = (const float*)d_in[2];
    const float* w2 = (const float*)d_in[3];
    const float* w3 = (const float*)d_in[4];
    float* out = (float*)d_out;

    zero_kernel<<<(NT * ND / 4 + 255) / 256, 256>>>(out);
    router_kernel<<<NT / 8, 256>>>(x, gw);
    scan_kernel<<<1, 32>>>();
    scatter_kernel<<<(NROWS + 255) / 256, 256>>>();

    dim3 g1(NH / G1_BN, NT / G1_BM, NE);   // (44, 64, 8) — empty m-tiles exit early
    gemm1_kernel<<<g1, 256>>>(x, w1, w3);

    dim3 g2(ND / G2_BN, NT / G2_BM, NE);   // (8, 64, 8)
    gemm2_kernel<<<g2, 256>>>(w2, out);
}

// round 8
// speedup vs baseline: 4.7297x; 1.3358x over previous
#include <cuda_runtime.h>
#include <cuda_fp16.h>
#include <math.h>
#include <stdint.h>

#define NT 8192          // tokens (B*S)
#define ND 1024          // model dim
#define NE 8             // experts
#define NH 2816          // hidden dim
#define NROWS (NT * 2)   // total (token, expert-slot) rows

// ---- device scratch (allocation-free) ----
__device__ int    g_counts[NE];
__device__ int    g_ctr[NE];
__device__ int    g_offsets[NE];
__device__ int    g_route_e[NROWS];
__device__ float  g_route_w[NROWS];
__device__ int    g_perm[NROWS];     // row -> token
__device__ float  g_pw[NROWS];       // row -> combine weight
__device__ __half g_h[(size_t)NROWS * NH];   // SwiGLU activations, 92 MB (fp16)

// ---------------------------------------------------------------------------
// fp16 mma helper: m16n8k16, row.col, f32 accum
// ---------------------------------------------------------------------------
__device__ __forceinline__ void mma_f16(float c[4], const uint32_t a[4], const uint32_t b[2]) {
    asm volatile(
        "mma.sync.aligned.m16n8k16.row.col.f32.f16.f16.f32 "
        "{%0,%1,%2,%3},{%4,%5,%6,%7},{%8,%9},{%0,%1,%2,%3};\n"
        : "+f"(c[0]), "+f"(c[1]), "+f"(c[2]), "+f"(c[3])
        : "r"(a[0]), "r"(a[1]), "r"(a[2]), "r"(a[3]), "r"(b[0]), "r"(b[1]));
}

// convert float4 -> 2x half2 packed as uint2, store 8B to smem
__device__ __forceinline__ void st_h4(__half* dst, float4 v) {
    __half2 h0 = __floats2half2_rn(v.x, v.y);
    __half2 h1 = __floats2half2_rn(v.z, v.w);
    uint2 u;
    u.x = *(uint32_t*)&h0;
    u.y = *(uint32_t*)&h1;
    *(uint2*)dst = u;
}

// ---------------------------------------------------------------------------
// 0) zero output + counters
// ---------------------------------------------------------------------------
__global__ void zero_kernel(float* __restrict__ out) {
    int i = blockIdx.x * blockDim.x + threadIdx.x;
    int n4 = NT * ND / 4;
    if (i < n4) ((float4*)out)[i] = make_float4(0.f, 0.f, 0.f, 0.f);
    if (i < NE) { g_counts[i] = 0; g_ctr[i] = 0; }
}

// ---------------------------------------------------------------------------
// 1) router: exact fp32 logits, top-2 + pair softmax
// ---------------------------------------------------------------------------
__global__ void router_kernel(const float* __restrict__ x,
                              const float* __restrict__ gw) {
    __shared__ float sg[NE * ND];
    int tid = threadIdx.x;
    for (int i = tid; i < NE * ND / 4; i += blockDim.x)
        ((float4*)sg)[i] = ((const float4*)gw)[i];
    __syncthreads();

    int lane = tid & 31;
    int t = blockIdx.x * 8 + (tid >> 5);
    if (t >= NT) return;

    const float4* xv = (const float4*)(x + (size_t)t * ND);
    float acc[NE];
#pragma unroll
    for (int e = 0; e < NE; e++) acc[e] = 0.f;
#pragma unroll
    for (int j = 0; j < ND / 128; j++) {
        int v = j * 32 + lane;
        float4 xx = xv[v];
#pragma unroll
        for (int e = 0; e < NE; e++) {
            float4 gg = ((const float4*)sg)[e * (ND / 4) + v];
            acc[e] += xx.x * gg.x + xx.y * gg.y + xx.z * gg.z + xx.w * gg.w;
        }
    }
#pragma unroll
    for (int e = 0; e < NE; e++)
#pragma unroll
        for (int o = 16; o > 0; o >>= 1)
            acc[e] += __shfl_xor_sync(0xffffffffu, acc[e], o);

    if (lane == 0) {
        int b0 = 0;
#pragma unroll
        for (int e = 1; e < NE; e++) if (acc[e] > acc[b0]) b0 = e;
        int b1 = (b0 == 0) ? 1 : 0;
#pragma unroll
        for (int e = 0; e < NE; e++)
            if (e != b0 && acc[e] > acc[b1]) b1 = e;
        float d  = acc[b1] - acc[b0];
        float e1 = expf(d);
        float s  = 1.f + e1;
        g_route_e[2 * t]     = b0;  g_route_w[2 * t]     = 1.f / s;
        g_route_e[2 * t + 1] = b1;  g_route_w[2 * t + 1] = e1 / s;
        atomicAdd(&g_counts[b0], 1);
        atomicAdd(&g_counts[b1], 1);
    }
}

__global__ void scan_kernel() {
    if (threadIdx.x == 0) {
        int o = 0;
        for (int e = 0; e < NE; e++) { g_offsets[e] = o; o += g_counts[e]; }
    }
}

__global__ void scatter_kernel() {
    int i = blockIdx.x * blockDim.x + threadIdx.x;
    if (i >= NROWS) return;
    int e = g_route_e[i];
    int p = atomicAdd(&g_ctr[e], 1);
    int r = g_offsets[e] + p;
    g_perm[r] = i >> 1;
    g_pw[r]   = g_route_w[i];
}

// ---------------------------------------------------------------------------
// GEMM1 (fp16 HMMA k16): gathered X @ {w1^T, w3^T}, SiLU-gate -> g_h (half)
// CTA 128 x (64+64), BK=32, 256 thr, warps 4(m) x 2(n), 32x32(x2 mats)/warp
// smem: As[128][40] half, Bs[128][40] half (rows 0-63 w1, 64-127 w3)
// ---------------------------------------------------------------------------
#define G1_SPAD 40

__global__ __launch_bounds__(256) void gemm1_kernel(
    const float* __restrict__ x,
    const float* __restrict__ w1,
    const float* __restrict__ w3) {
    int e   = blockIdx.z;
    int cnt = g_counts[e];
    int m0  = blockIdx.y * 128;
    if (m0 >= cnt) return;
    int n0  = blockIdx.x * 64;
    int off = g_offsets[e];

    __shared__ __half As[128][G1_SPAD];
    __shared__ __half Bs[128][G1_SPAD];
    __shared__ int    stok[128];

    int tid = threadIdx.x;
    if (tid < 128)
        stok[tid] = (m0 + tid < cnt) ? g_perm[off + m0 + tid] : -1;
    __syncthreads();

    const float* w1e = w1 + (size_t)e * NH * ND;
    const float* w3e = w3 + (size_t)e * NH * ND;

    int rb    = tid >> 3;        // 0..31
    int chunk = tid & 3 ? 0 : 0; // placeholder to keep regs tight
    chunk = tid & 7;             // 0..7 (16B chunk in 128B row)

    const float* ap[4];
    int arow[4];
#pragma unroll
    for (int i = 0; i < 4; i++) {
        arow[i] = rb + 32 * i;
        int tok = stok[arow[i]];
        ap[i] = (tok >= 0) ? (x + (size_t)tok * ND + chunk * 4) : nullptr;
    }
    const float* b1p[2];
    const float* b3p[2];
    int brow[2];
#pragma unroll
    for (int i = 0; i < 2; i++) {
        brow[i] = rb + 32 * i;                     // 0..63
        b1p[i] = w1e + (size_t)(n0 + brow[i]) * ND + chunk * 4;
        b3p[i] = w3e + (size_t)(n0 + brow[i]) * ND + chunk * 4;
    }

    int lane = tid & 31, wid = tid >> 5;
    int wm = wid >> 1, wn = wid & 1;
    int g = lane >> 2, t = lane & 3;

    float acc1[2][4][4], acc3[2][4][4];
#pragma unroll
    for (int mi = 0; mi < 2; mi++)
#pragma unroll
        for (int ni = 0; ni < 4; ni++)
#pragma unroll
            for (int q = 0; q < 4; q++) { acc1[mi][ni][q] = 0.f; acc3[mi][ni][q] = 0.f; }

    const float4 z4 = make_float4(0.f, 0.f, 0.f, 0.f);
    float4 aR[4], b1R[2], b3R[2];
#pragma unroll
    for (int i = 0; i < 4; i++) aR[i] = ap[i] ? *(const float4*)(ap[i]) : z4;
#pragma unroll
    for (int i = 0; i < 2; i++) { b1R[i] = *(const float4*)(b1p[i]); b3R[i] = *(const float4*)(b3p[i]); }

    const int KT = ND / 32;   // 32
    for (int kt = 0; kt < KT; kt++) {
        __syncthreads();
#pragma unroll
        for (int i = 0; i < 4; i++) st_h4(&As[arow[i]][chunk * 4], aR[i]);
#pragma unroll
        for (int i = 0; i < 2; i++) {
            st_h4(&Bs[brow[i]][chunk * 4],      b1R[i]);
            st_h4(&Bs[64 + brow[i]][chunk * 4], b3R[i]);
        }
        __syncthreads();

        if (kt + 1 < KT) {
            int ko = (kt + 1) * 32;
#pragma unroll
            for (int i = 0; i < 4; i++) aR[i] = ap[i] ? *(const float4*)(ap[i] + ko) : z4;
#pragma unroll
            for (int i = 0; i < 2; i++) { b1R[i] = *(const float4*)(b1p[i] + ko); b3R[i] = *(const float4*)(b3p[i] + ko); }
        }

#pragma unroll
        for (int kc = 0; kc < 2; kc++) {          // two k16 chunks
            int kk = kc * 16;
            uint32_t af[2][4];
#pragma unroll
            for (int mi = 0; mi < 2; mi++) {
                int ar = wm * 32 + mi * 16;
                af[mi][0] = *(const uint32_t*)&As[ar + g][kk + 2 * t];
                af[mi][1] = *(const uint32_t*)&As[ar + g + 8][kk + 2 * t];
                af[mi][2] = *(const uint32_t*)&As[ar + g][kk + 2 * t + 8];
                af[mi][3] = *(const uint32_t*)&As[ar + g + 8][kk + 2 * t + 8];
            }
            uint32_t bf1[4][2], bf3[4][2];
#pragma unroll
            for (int ni = 0; ni < 4; ni++) {
                int br = wn * 32 + ni * 8 + g;
                bf1[ni][0] = *(const uint32_t*)&Bs[br][kk + 2 * t];
                bf1[ni][1] = *(const uint32_t*)&Bs[br][kk + 2 * t + 8];
                bf3[ni][0] = *(const uint32_t*)&Bs[64 + br][kk + 2 * t];
                bf3[ni][1] = *(const uint32_t*)&Bs[64 + br][kk + 2 * t + 8];
            }
#pragma unroll
            for (int mi = 0; mi < 2; mi++)
#pragma unroll
                for (int ni = 0; ni < 4; ni++) {
                    mma_f16(acc1[mi][ni], af[mi], bf1[ni]);
                    mma_f16(acc3[mi][ni], af[mi], bf3[ni]);
                }
        }
    }

    // epilogue: silu(acc1)*acc3 -> half2 -> g_h
#pragma unroll
    for (int mi = 0; mi < 2; mi++) {
#pragma unroll
        for (int half = 0; half < 2; half++) {
            int mrow = wm * 32 + mi * 16 + g + half * 8;
            int m = m0 + mrow;
            if (m >= cnt) continue;
            size_t r = (size_t)(off + m);
#pragma unroll
            for (int ni = 0; ni < 4; ni++) {
                float a0 = acc1[mi][ni][half * 2 + 0];
                float a1 = acc1[mi][ni][half * 2 + 1];
                float v0 = (a0 / (1.f + __expf(-a0))) * acc3[mi][ni][half * 2 + 0];
                float v1 = (a1 / (1.f + __expf(-a1))) * acc3[mi][ni][half * 2 + 1];
                int col = n0 + wn * 32 + ni * 8 + 2 * t;
                __half2 hv = __floats2half2_rn(v0, v1);
                *(__half2*)(g_h + r * NH + col) = hv;
            }
        }
    }
}

// ---------------------------------------------------------------------------
// GEMM2 (fp16 HMMA k16): g_h(half) @ w2^T, * combine weight, atomicAdd
// CTA 128 x 128, BK=32, 256 thr, warps 2(m) x 4(n), 64x32/warp
// ---------------------------------------------------------------------------
#define G2_SPAD 40

__global__ __launch_bounds__(256) void gemm2_kernel(
    const float* __restrict__ w2, float* __restrict__ out) {
    int e   = blockIdx.z;
    int cnt = g_counts[e];
    int m0  = blockIdx.y * 128;
    if (m0 >= cnt) return;
    int n0  = blockIdx.x * 128;
    int off = g_offsets[e];

    __shared__ __half As[128][G2_SPAD];
    __shared__ __half Bs[128][G2_SPAD];

    int tid = threadIdx.x;
    const float* w2e = w2 + (size_t)e * ND * NH;

    // A loader: g_h is half; row = tid>>2 (+64), 16B chunk c2 = tid&3
    int rowA = tid >> 2, c2 = tid & 3;
    const __half* hp[2];
    int harow[2];
#pragma unroll
    for (int i = 0; i < 2; i++) {
        harow[i] = rowA + 64 * i;
        bool valid = (m0 + harow[i]) < cnt;
        hp[i] = valid ? (g_h + (size_t)(off + m0 + harow[i]) * NH + c2 * 8) : nullptr;
    }

    // B loader: w2 fp32; row = tid>>3 (+32i), 16B chunk = tid&7
    int rb = tid >> 3, chunk = tid & 7;
    const float* bp[4];
    int brow[4];
#pragma unroll
    for (int i = 0; i < 4; i++) {
        brow[i] = rb + 32 * i;
        bp[i] = w2e + (size_t)(n0 + brow[i]) * NH + chunk * 4;
    }

    int lane = tid & 31, wid = tid >> 5;
    int wm = wid >> 2, wn = wid & 3;
    int g = lane >> 2, t = lane & 3;

    float acc[4][4][4];
#pragma unroll
    for (int mi = 0; mi < 4; mi++)
#pragma unroll
        for (int ni = 0; ni < 4; ni++)
#pragma unroll
            for (int q = 0; q < 4; q++) acc[mi][ni][q] = 0.f;

    const uint4 zu4 = make_uint4(0u, 0u, 0u, 0u);
    const float4 z4 = make_float4(0.f, 0.f, 0.f, 0.f);
    uint4 aR[2];
    float4 bR[4];
#pragma unroll
    for (int i = 0; i < 2; i++) aR[i] = hp[i] ? *(const uint4*)(hp[i]) : zu4;
#pragma unroll
    for (int i = 0; i < 4; i++) bR[i] = *(const float4*)(bp[i]);

    const int KT = NH / 32;   // 88
    for (int kt = 0; kt < KT; kt++) {
        __syncthreads();
#pragma unroll
        for (int i = 0; i < 2; i++) {
            // 16B of halves -> two 8B smem stores (stride-40 rows are 8B aligned)
            uint2 lo = make_uint2(aR[i].x, aR[i].y);
            uint2 hi = make_uint2(aR[i].z, aR[i].w);
            *(uint2*)&As[harow[i]][c2 * 8]     = lo;
            *(uint2*)&As[harow[i]][c2 * 8 + 4] = hi;
        }
#pragma unroll
        for (int i = 0; i < 4; i++) st_h4(&Bs[brow[i]][chunk * 4], bR[i]);
        __syncthreads();

        if (kt + 1 < KT) {
            int ko = (kt + 1) * 32;
#pragma unroll
            for (int i = 0; i < 2; i++) aR[i] = hp[i] ? *(const uint4*)(hp[i] + ko) : zu4;
#pragma unroll
            for (int i = 0; i < 4; i++) bR[i] = *(const float4*)(bp[i] + ko);
        }

#pragma unroll
        for (int kc = 0; kc < 2; kc++) {
            int kk = kc * 16;
            uint32_t af[4][4];
#pragma unroll
            for (int mi = 0; mi < 4; mi++) {
                int ar = wm * 64 + mi * 16;
                af[mi][0] = *(const uint32_t*)&As[ar + g][kk + 2 * t];
                af[mi][1] = *(const uint32_t*)&As[ar + g + 8][kk + 2 * t];
                af[mi][2] = *(const uint32_t*)&As[ar + g][kk + 2 * t + 8];
                af[mi][3] = *(const uint32_t*)&As[ar + g + 8][kk + 2 * t + 8];
            }
            uint32_t bf[4][2];
#pragma unroll
            for (int ni = 0; ni < 4; ni++) {
                int br = wn * 32 + ni * 8 + g;
                bf[ni][0] = *(const uint32_t*)&Bs[br][kk + 2 * t];
                bf[ni][1] = *(const uint32_t*)&Bs[br][kk + 2 * t + 8];
            }
#pragma unroll
            for (int mi = 0; mi < 4; mi++)
#pragma unroll
                for (int ni = 0; ni < 4; ni++)
                    mma_f16(acc[mi][ni], af[mi], bf[ni]);
        }
    }

    // epilogue: scale by combine weight, atomicAdd into out
#pragma unroll
    for (int mi = 0; mi < 4; mi++) {
#pragma unroll
        for (int half = 0; half < 2; half++) {
            int mrow = wm * 64 + mi * 16 + g + half * 8;
            int m = m0 + mrow;
            if (m >= cnt) continue;
            int r = off + m;
            int tok = g_perm[r];
            float w = g_pw[r];
            float* orow = out + (size_t)tok * ND;
#pragma unroll
            for (int ni = 0; ni < 4; ni++) {
                int col = n0 + wn * 32 + ni * 8 + 2 * t;
                atomicAdd(orow + col,     w * acc[mi][ni][half * 2 + 0]);
                atomicAdd(orow + col + 1, w * acc[mi][ni][half * 2 + 1]);
            }
        }
    }
}

// ---------------------------------------------------------------------------
extern "C" void kernel_launch(void* const* d_in, const int* in_sizes, int n_in,
                              void* d_out, int out_size) {
    const float* x  = (const float*)d_in[0];
    const float* gw = (const float*)d_in[1];
    const float* w1 = (const float*)d_in[2];
    const float* w2 = (const float*)d_in[3];
    const float* w3 = (const float*)d_in[4];
    float* out = (float*)d_out;

    zero_kernel<<<(NT * ND / 4 + 255) / 256, 256>>>(out);
    router_kernel<<<NT / 8, 256>>>(x, gw);
    scan_kernel<<<1, 32>>>();
    scatter_kernel<<<(NROWS + 255) / 256, 256>>>();

    dim3 g1(NH / 64, NROWS / 128, NE);   // (44, 128, 8) — empty m-tiles exit early
    gemm1_kernel<<<g1, 256>>>(x, w1, w3);

    dim3 g2(ND / 128, NROWS / 128, NE);  // (8, 128, 8)
    gemm2_kernel<<<g2, 256>>>(w2, out);
}

// round 9
// speedup vs baseline: 6.8471x; 1.4477x over previous
#include <cuda_runtime.h>
#include <cuda_fp16.h>
#include <math.h>
#include <stdint.h>

#define NT 8192          // tokens (B*S)
#define ND 1024          // model dim
#define NE 8             // experts
#define NH 2816          // hidden dim
#define NROWS (NT * 2)   // total (token, expert-slot) rows
#define WELEM (NE * NH * ND)   // 23,068,672 elements per weight tensor

// ---- device scratch (allocation-free) ----
__device__ int    g_counts[NE];
__device__ int    g_ctr[NE];
__device__ int    g_offsets[NE];
__device__ int    g_route_e[NROWS];
__device__ float  g_route_w[NROWS];
__device__ int    g_perm[NROWS];
__device__ float  g_pw[NROWS];
__device__ __half g_h[(size_t)NROWS * NH];     // 92 MB
__device__ __half g_xh[(size_t)NT * ND];       // 16.8 MB
__device__ __half g_w1h[(size_t)WELEM];        // 46.1 MB
__device__ __half g_w3h[(size_t)WELEM];        // 46.1 MB
__device__ __half g_w2h[(size_t)WELEM];        // 46.1 MB

// ---------------------------------------------------------------------------
// helpers
// ---------------------------------------------------------------------------
__device__ __forceinline__ uint32_t smem_u32(const void* p) {
    uint32_t a;
    asm("{ .reg .u64 t; cvta.to.shared.u64 t, %1; cvt.u32.u64 %0, t; }" : "=r"(a) : "l"(p));
    return a;
}

__device__ __forceinline__ void mma_f16(float c[4], const uint32_t a[4], const uint32_t b[2]) {
    asm volatile(
        "mma.sync.aligned.m16n8k16.row.col.f32.f16.f16.f32 "
        "{%0,%1,%2,%3},{%4,%5,%6,%7},{%8,%9},{%0,%1,%2,%3};\n"
        : "+f"(c[0]), "+f"(c[1]), "+f"(c[2]), "+f"(c[3])
        : "r"(a[0]), "r"(a[1]), "r"(a[2]), "r"(a[3]), "r"(b[0]), "r"(b[1]));
}

__device__ __forceinline__ void ldsm_x4(uint32_t r[4], uint32_t addr) {
    asm volatile("ldmatrix.sync.aligned.m8n8.x4.shared.b16 {%0,%1,%2,%3}, [%4];"
        : "=r"(r[0]), "=r"(r[1]), "=r"(r[2]), "=r"(r[3]) : "r"(addr));
}

// ---------------------------------------------------------------------------
// fp32 -> fp16 bulk convert
// ---------------------------------------------------------------------------
__global__ void cvt_kernel(const float4* __restrict__ src, uint2* __restrict__ dst, int n4) {
    int i = blockIdx.x * blockDim.x + threadIdx.x;
    if (i < n4) {
        float4 v = src[i];
        __half2 h0 = __floats2half2_rn(v.x, v.y);
        __half2 h1 = __floats2half2_rn(v.z, v.w);
        dst[i] = make_uint2(*(uint32_t*)&h0, *(uint32_t*)&h1);
    }
}

// ---------------------------------------------------------------------------
// 0) zero output + counters
// ---------------------------------------------------------------------------
__global__ void zero_kernel(float* __restrict__ out) {
    int i = blockIdx.x * blockDim.x + threadIdx.x;
    int n4 = NT * ND / 4;
    if (i < n4) ((float4*)out)[i] = make_float4(0.f, 0.f, 0.f, 0.f);
    if (i < NE) { g_counts[i] = 0; g_ctr[i] = 0; }
}

// ---------------------------------------------------------------------------
// 1) router: exact fp32 logits, top-2 + pair softmax
// ---------------------------------------------------------------------------
__global__ void router_kernel(const float* __restrict__ x,
                              const float* __restrict__ gw) {
    __shared__ float sg[NE * ND];
    int tid = threadIdx.x;
    for (int i = tid; i < NE * ND / 4; i += blockDim.x)
        ((float4*)sg)[i] = ((const float4*)gw)[i];
    __syncthreads();

    int lane = tid & 31;
    int t = blockIdx.x * 8 + (tid >> 5);
    if (t >= NT) return;

    const float4* xv = (const float4*)(x + (size_t)t * ND);
    float acc[NE];
#pragma unroll
    for (int e = 0; e < NE; e++) acc[e] = 0.f;
#pragma unroll
    for (int j = 0; j < ND / 128; j++) {
        int v = j * 32 + lane;
        float4 xx = xv[v];
#pragma unroll
        for (int e = 0; e < NE; e++) {
            float4 gg = ((const float4*)sg)[e * (ND / 4) + v];
            acc[e] += xx.x * gg.x + xx.y * gg.y + xx.z * gg.z + xx.w * gg.w;
        }
    }
#pragma unroll
    for (int e = 0; e < NE; e++)
#pragma unroll
        for (int o = 16; o > 0; o >>= 1)
            acc[e] += __shfl_xor_sync(0xffffffffu, acc[e], o);

    if (lane == 0) {
        int b0 = 0;
#pragma unroll
        for (int e = 1; e < NE; e++) if (acc[e] > acc[b0]) b0 = e;
        int b1 = (b0 == 0) ? 1 : 0;
#pragma unroll
        for (int e = 0; e < NE; e++)
            if (e != b0 && acc[e] > acc[b1]) b1 = e;
        float d  = acc[b1] - acc[b0];
        float e1 = expf(d);
        float s  = 1.f + e1;
        g_route_e[2 * t]     = b0;  g_route_w[2 * t]     = 1.f / s;
        g_route_e[2 * t + 1] = b1;  g_route_w[2 * t + 1] = e1 / s;
        atomicAdd(&g_counts[b0], 1);
        atomicAdd(&g_counts[b1], 1);
    }
}

__global__ void scan_kernel() {
    if (threadIdx.x == 0) {
        int o = 0;
        for (int e = 0; e < NE; e++) { g_offsets[e] = o; o += g_counts[e]; }
    }
}

__global__ void scatter_kernel() {
    int i = blockIdx.x * blockDim.x + threadIdx.x;
    if (i >= NROWS) return;
    int e = g_route_e[i];
    int p = atomicAdd(&g_ctr[e], 1);
    int r = g_offsets[e] + p;
    g_perm[r] = i >> 1;
    g_pw[r]   = g_route_w[i];
}

// ---------------------------------------------------------------------------
// GEMM1: xh[gathered 128, K=1024] @ {w1h,w3h}[64,K]^T -> silu-gate -> g_h
// warps 4(m)x2(n), warp tile 32m x 32n per mat; BK=32; ldmatrix frags
// ---------------------------------------------------------------------------
#define SPAD 40   // halves per smem row (32 data + 8 pad); 80 B stride

__global__ __launch_bounds__(256) void gemm1_kernel() {
    int e   = blockIdx.z;
    int cnt = g_counts[e];
    int m0  = blockIdx.x * 128;          // m fastest -> B-slice reuse in L2
    if (m0 >= cnt) return;
    int n0  = blockIdx.y * 64;
    int off = g_offsets[e];

    __shared__ __half As[128][SPAD];
    __shared__ __half Bs[128][SPAD];     // rows 0-63: w1, 64-127: w3
    __shared__ int    stok[128];

    int tid = threadIdx.x;
    if (tid < 128)
        stok[tid] = (m0 + tid < cnt) ? g_perm[off + m0 + tid] : -1;
    __syncthreads();

    const __half* w1e = g_w1h + (size_t)e * NH * ND;
    const __half* w3e = g_w3h + (size_t)e * NH * ND;

    // loaders: rows r and r+64, chunk ch (8 halves = 16B)
    int r  = tid >> 2;          // 0..63
    int ch = tid & 3;           // 0..3
    const __half* ap[2];
#pragma unroll
    for (int i = 0; i < 2; i++) {
        int tok = stok[r + 64 * i];
        ap[i] = (tok >= 0) ? (g_xh + (size_t)tok * ND + ch * 8) : nullptr;
    }
    const __half* bp0 = w1e + (size_t)(n0 + r) * ND + ch * 8;   // -> Bs row r
    const __half* bp1 = w3e + (size_t)(n0 + r) * ND + ch * 8;   // -> Bs row r+64

    int lane = tid & 31, wid = tid >> 5;
    int wm = wid >> 1, wn = wid & 1;
    int g = lane >> 2, t = lane & 3;

    // ldmatrix base addresses (byte offsets; row stride 80B)
    uint32_t aBase = smem_u32(&As[wm * 32 + (lane & 15)][8 * (lane >> 4)]);
    uint32_t bBase = smem_u32(&Bs[(lane & 7) + 8 * (lane >> 4)][8 * ((lane >> 3) & 1)]);

    float acc1[2][4][4], acc3[2][4][4];
#pragma unroll
    for (int mi = 0; mi < 2; mi++)
#pragma unroll
        for (int ni = 0; ni < 4; ni++)
#pragma unroll
            for (int q = 0; q < 4; q++) { acc1[mi][ni][q] = 0.f; acc3[mi][ni][q] = 0.f; }

    const uint4 zu4 = make_uint4(0u, 0u, 0u, 0u);
    uint4 aR[2], bR[2];
#pragma unroll
    for (int i = 0; i < 2; i++) aR[i] = ap[i] ? *(const uint4*)ap[i] : zu4;
    bR[0] = *(const uint4*)bp0;
    bR[1] = *(const uint4*)bp1;

    const int KT = ND / 32;   // 32
    for (int kt = 0; kt < KT; kt++) {
        __syncthreads();
#pragma unroll
        for (int i = 0; i < 2; i++) *(uint4*)&As[r + 64 * i][ch * 8] = aR[i];
        *(uint4*)&Bs[r][ch * 8]      = bR[0];
        *(uint4*)&Bs[r + 64][ch * 8] = bR[1];
        __syncthreads();

        if (kt + 1 < KT) {
            int ko = (kt + 1) * 32;
#pragma unroll
            for (int i = 0; i < 2; i++) aR[i] = ap[i] ? *(const uint4*)(ap[i] + ko) : zu4;
            bR[0] = *(const uint4*)(bp0 + ko);
            bR[1] = *(const uint4*)(bp1 + ko);
        }

#pragma unroll
        for (int kc = 0; kc < 2; kc++) {
            uint32_t kb = kc * 32;   // 16 halves = 32 B
            uint32_t af[2][4], bf1[2][4], bf3[2][4];
            ldsm_x4(af[0], aBase + kb);
            ldsm_x4(af[1], aBase + kb + 16 * 80);
            uint32_t bw = (uint32_t)(wn * 32) * 80;
            ldsm_x4(bf1[0], bBase + kb + bw);
            ldsm_x4(bf1[1], bBase + kb + bw + 16 * 80);
            ldsm_x4(bf3[0], bBase + kb + bw + 64 * 80);
            ldsm_x4(bf3[1], bBase + kb + bw + 80 * 80);
#pragma unroll
            for (int mi = 0; mi < 2; mi++)
#pragma unroll
                for (int j = 0; j < 4; j++) {
                    mma_f16(acc1[mi][j], af[mi], &bf1[j >> 1][2 * (j & 1)]);
                    mma_f16(acc3[mi][j], af[mi], &bf3[j >> 1][2 * (j & 1)]);
                }
        }
    }

    // epilogue: silu(acc1)*acc3 -> half2 -> g_h
#pragma unroll
    for (int mi = 0; mi < 2; mi++) {
#pragma unroll
        for (int hf = 0; hf < 2; hf++) {
            int mrow = wm * 32 + mi * 16 + g + hf * 8;
            int m = m0 + mrow;
            if (m >= cnt) continue;
            size_t rr = (size_t)(off + m);
#pragma unroll
            for (int ni = 0; ni < 4; ni++) {
                float a0 = acc1[mi][ni][hf * 2 + 0];
                float a1 = acc1[mi][ni][hf * 2 + 1];
                float v0 = (a0 / (1.f + __expf(-a0))) * acc3[mi][ni][hf * 2 + 0];
                float v1 = (a1 / (1.f + __expf(-a1))) * acc3[mi][ni][hf * 2 + 1];
                int col = n0 + wn * 32 + ni * 8 + 2 * t;
                *(__half2*)(g_h + rr * NH + col) = __floats2half2_rn(v0, v1);
            }
        }
    }
}

// ---------------------------------------------------------------------------
// GEMM2: g_h[128, K=2816] @ w2h[128, K]^T * pw -> atomicAdd out
// warps 2(m)x4(n), warp tile 64m x 32n; BK=32; ldmatrix frags
// ---------------------------------------------------------------------------
__global__ __launch_bounds__(256) void gemm2_kernel(float* __restrict__ out) {
    int e   = blockIdx.z;
    int cnt = g_counts[e];
    int m0  = blockIdx.y * 128;
    if (m0 >= cnt) return;
    int n0  = blockIdx.x * 128;          // n fastest -> A-slice reuse in L2
    int off = g_offsets[e];

    __shared__ __half As[128][SPAD];
    __shared__ __half Bs[128][SPAD];

    int tid = threadIdx.x;
    const __half* w2e = g_w2h + (size_t)e * ND * NH;

    int r  = tid >> 2;
    int ch = tid & 3;
    const __half* ap[2];
#pragma unroll
    for (int i = 0; i < 2; i++) {
        bool valid = (m0 + r + 64 * i) < cnt;
        ap[i] = valid ? (g_h + (size_t)(off + m0 + r + 64 * i) * NH + ch * 8) : nullptr;
    }
    const __half* bp[2];
#pragma unroll
    for (int i = 0; i < 2; i++)
        bp[i] = w2e + (size_t)(n0 + r + 64 * i) * NH + ch * 8;

    int lane = tid & 31, wid = tid >> 5;
    int wm = wid >> 2, wn = wid & 3;
    int g = lane >> 2, t = lane & 3;

    uint32_t aBase = smem_u32(&As[wm * 64 + (lane & 15)][8 * (lane >> 4)]);
    uint32_t bBase = smem_u32(&Bs[(lane & 7) + 8 * (lane >> 4)][8 * ((lane >> 3) & 1)]);

    float acc[4][4][4];
#pragma unroll
    for (int mi = 0; mi < 4; mi++)
#pragma unroll
        for (int ni = 0; ni < 4; ni++)
#pragma unroll
            for (int q = 0; q < 4; q++) acc[mi][ni][q] = 0.f;

    const uint4 zu4 = make_uint4(0u, 0u, 0u, 0u);
    uint4 aR[2], bR[2];
#pragma unroll
    for (int i = 0; i < 2; i++) {
        aR[i] = ap[i] ? *(const uint4*)ap[i] : zu4;
        bR[i] = *(const uint4*)bp[i];
    }

    const int KT = NH / 32;   // 88
    for (int kt = 0; kt < KT; kt++) {
        __syncthreads();
#pragma unroll
        for (int i = 0; i < 2; i++) {
            *(uint4*)&As[r + 64 * i][ch * 8] = aR[i];
            *(uint4*)&Bs[r + 64 * i][ch * 8] = bR[i];
        }
        __syncthreads();

        if (kt + 1 < KT) {
            int ko = (kt + 1) * 32;
#pragma unroll
            for (int i = 0; i < 2; i++) {
                aR[i] = ap[i] ? *(const uint4*)(ap[i] + ko) : zu4;
                bR[i] = *(const uint4*)(bp[i] + ko);
            }
        }

#pragma unroll
        for (int kc = 0; kc < 2; kc++) {
            uint32_t kb = kc * 32;
            uint32_t af[4][4], bf[2][4];
#pragma unroll
            for (int mi = 0; mi < 4; mi++)
                ldsm_x4(af[mi], aBase + kb + (uint32_t)(mi * 16) * 80);
            uint32_t bw = (uint32_t)(wn * 32) * 80;
            ldsm_x4(bf[0], bBase + kb + bw);
            ldsm_x4(bf[1], bBase + kb + bw + 16 * 80);
#pragma unroll
            for (int mi = 0; mi < 4; mi++)
#pragma unroll
                for (int j = 0; j < 4; j++)
                    mma_f16(acc[mi][j], af[mi], &bf[j >> 1][2 * (j & 1)]);
        }
    }

    // epilogue: scale by combine weight, atomicAdd into out
#pragma unroll
    for (int mi = 0; mi < 4; mi++) {
#pragma unroll
        for (int hf = 0; hf < 2; hf++) {
            int mrow = wm * 64 + mi * 16 + g + hf * 8;
            int m = m0 + mrow;
            if (m >= cnt) continue;
            int rr = off + m;
            int tok = g_perm[rr];
            float w = g_pw[rr];
            float* orow = out + (size_t)tok * ND;
#pragma unroll
            for (int ni = 0; ni < 4; ni++) {
                int col = n0 + wn * 32 + ni * 8 + 2 * t;
                atomicAdd(orow + col,     w * acc[mi][ni][hf * 2 + 0]);
                atomicAdd(orow + col + 1, w * acc[mi][ni][hf * 2 + 1]);
            }
        }
    }
}

// ---------------------------------------------------------------------------
extern "C" void kernel_launch(void* const* d_in, const int* in_sizes, int n_in,
                              void* d_out, int out_size) {
    const float* x  = (const float*)d_in[0];
    const float* gw = (const float*)d_in[1];
    const float* w1 = (const float*)d_in[2];
    const float* w2 = (const float*)d_in[3];
    const float* w3 = (const float*)d_in[4];
    float* out = (float*)d_out;

    // fp32 -> fp16 staging (x + all weights)
    {
        __half* dxh; cudaGetSymbolAddress((void**)&dxh, g_xh);
        __half* dw1; cudaGetSymbolAddress((void**)&dw1, g_w1h);
        __half* dw3; cudaGetSymbolAddress((void**)&dw3, g_w3h);
        __half* dw2; cudaGetSymbolAddress((void**)&dw2, g_w2h);
        int nx = NT * ND / 4, nw = WELEM / 4;
        cvt_kernel<<<(nx + 255) / 256, 256>>>((const float4*)x,  (uint2*)dxh, nx);
        cvt_kernel<<<(nw + 255) / 256, 256>>>((const float4*)w1, (uint2*)dw1, nw);
        cvt_kernel<<<(nw + 255) / 256, 256>>>((const float4*)w3, (uint2*)dw3, nw);
        cvt_kernel<<<(nw + 255) / 256, 256>>>((const float4*)w2, (uint2*)dw2, nw);
    }

    zero_kernel<<<(NT * ND / 4 + 255) / 256, 256>>>(out);
    router_kernel<<<NT / 8, 256>>>(x, gw);
    scan_kernel<<<1, 32>>>();
    scatter_kernel<<<(NROWS + 255) / 256, 256>>>();

    dim3 g1(NROWS / 128, NH / 64, NE);   // m fastest (B L2 reuse); (128, 44, 8)
    gemm1_kernel<<<g1, 256>>>();

    dim3 g2(ND / 128, NROWS / 128, NE);  // n fastest (A L2 reuse); (8, 128, 8)
    gemm2_kernel<<<g2, 256>>>(out);
}

// round 10
// speedup vs baseline: 7.5311x; 1.0999x over previous
#include <cuda_runtime.h>
#include <cuda_fp16.h>
#include <math.h>
#include <stdint.h>

#define NT 8192          // tokens (B*S)
#define ND 1024          // model dim
#define NE 8             // experts
#define NH 2816          // hidden dim
#define NROWS (NT * 2)   // total (token, expert-slot) rows
#define WELEM (NE * NH * ND)
#define NW4 (WELEM / 4)          // 5,767,168
#define NX4 (NT * ND / 4)        // 2,097,152

// ---- device scratch (allocation-free) ----
__device__ int    g_counts[NE];
__device__ int    g_ctr[NE];
__device__ int    g_offsets[NE];
__device__ int    g_route_e[NROWS];
__device__ float  g_route_w[NROWS];
__device__ int    g_perm[NROWS];
__device__ float  g_pw[NROWS];
__device__ __half g_h[(size_t)NROWS * NH];
__device__ __half g_xh[(size_t)NT * ND];
__device__ __half g_w1h[(size_t)WELEM];
__device__ __half g_w3h[(size_t)WELEM];
__device__ __half g_w2h[(size_t)WELEM];

// ---------------------------------------------------------------------------
// helpers
// ---------------------------------------------------------------------------
__device__ __forceinline__ uint32_t smem_u32(const void* p) {
    uint32_t a;
    asm("{ .reg .u64 t; cvta.to.shared.u64 t, %1; cvt.u32.u64 %0, t; }" : "=r"(a) : "l"(p));
    return a;
}
__device__ __forceinline__ void mma_f16(float c[4], const uint32_t a[4], const uint32_t b[2]) {
    asm volatile(
        "mma.sync.aligned.m16n8k16.row.col.f32.f16.f16.f32 "
        "{%0,%1,%2,%3},{%4,%5,%6,%7},{%8,%9},{%0,%1,%2,%3};\n"
        : "+f"(c[0]), "+f"(c[1]), "+f"(c[2]), "+f"(c[3])
        : "r"(a[0]), "r"(a[1]), "r"(a[2]), "r"(a[3]), "r"(b[0]), "r"(b[1]));
}
__device__ __forceinline__ void ldsm_x4(uint32_t r[4], uint32_t addr) {
    asm volatile("ldmatrix.sync.aligned.m8n8.x4.shared.b16 {%0,%1,%2,%3}, [%4];"
        : "=r"(r[0]), "=r"(r[1]), "=r"(r[2]), "=r"(r[3]) : "r"(addr));
}
__device__ __forceinline__ void cpa16(uint32_t dst, const void* src, int bytes) {
    asm volatile("cp.async.cg.shared.global [%0], [%1], 16, %2;"
        :: "r"(dst), "l"(src), "r"(bytes) : "memory");
}
#define CPA_COMMIT() asm volatile("cp.async.commit_group;" ::: "memory")
#define CPA_WAIT1()  asm volatile("cp.async.wait_group 1;" ::: "memory")

// ---------------------------------------------------------------------------
// prep: fp32->fp16 of w1/w3/w2/x + zero out + zero counters (one kernel)
// ---------------------------------------------------------------------------
__global__ void prep_kernel(const float4* __restrict__ x,
                            const float4* __restrict__ w1,
                            const float4* __restrict__ w2,
                            const float4* __restrict__ w3,
                            float4* __restrict__ out) {
    int i = blockIdx.x * blockDim.x + threadIdx.x;
    int rgn = blockIdx.y;
    const float4* src;
    uint2* dst;
    if (rgn == 0)      { if (i >= NW4) return; src = w1; dst = (uint2*)g_w1h; }
    else if (rgn == 1) { if (i >= NW4) return; src = w3; dst = (uint2*)g_w3h; }
    else if (rgn == 2) { if (i >= NW4) return; src = w2; dst = (uint2*)g_w2h; }
    else {
        if (i < NE) { g_counts[i] = 0; g_ctr[i] = 0; }
        if (i >= NX4) return;
        out[i] = make_float4(0.f, 0.f, 0.f, 0.f);
        src = x; dst = (uint2*)g_xh;
    }
    float4 v = src[i];
    __half2 h0 = __floats2half2_rn(v.x, v.y);
    __half2 h1 = __floats2half2_rn(v.z, v.w);
    dst[i] = make_uint2(*(uint32_t*)&h0, *(uint32_t*)&h1);
}

// ---------------------------------------------------------------------------
// router: exact fp32 logits, top-2 + pair softmax
// ---------------------------------------------------------------------------
__global__ void router_kernel(const float* __restrict__ x,
                              const float* __restrict__ gw) {
    __shared__ float sg[NE * ND];
    int tid = threadIdx.x;
    for (int i = tid; i < NE * ND / 4; i += blockDim.x)
        ((float4*)sg)[i] = ((const float4*)gw)[i];
    __syncthreads();

    int lane = tid & 31;
    int t = blockIdx.x * 8 + (tid >> 5);
    if (t >= NT) return;

    const float4* xv = (const float4*)(x + (size_t)t * ND);
    float acc[NE];
#pragma unroll
    for (int e = 0; e < NE; e++) acc[e] = 0.f;
#pragma unroll
    for (int j = 0; j < ND / 128; j++) {
        int v = j * 32 + lane;
        float4 xx = xv[v];
#pragma unroll
        for (int e = 0; e < NE; e++) {
            float4 gg = ((const float4*)sg)[e * (ND / 4) + v];
            acc[e] += xx.x * gg.x + xx.y * gg.y + xx.z * gg.z + xx.w * gg.w;
        }
    }
#pragma unroll
    for (int e = 0; e < NE; e++)
#pragma unroll
        for (int o = 16; o > 0; o >>= 1)
            acc[e] += __shfl_xor_sync(0xffffffffu, acc[e], o);

    if (lane == 0) {
        int b0 = 0;
#pragma unroll
        for (int e = 1; e < NE; e++) if (acc[e] > acc[b0]) b0 = e;
        int b1 = (b0 == 0) ? 1 : 0;
#pragma unroll
        for (int e = 0; e < NE; e++)
            if (e != b0 && acc[e] > acc[b1]) b1 = e;
        float d  = acc[b1] - acc[b0];
        float e1 = expf(d);
        float s  = 1.f + e1;
        g_route_e[2 * t]     = b0;  g_route_w[2 * t]     = 1.f / s;
        g_route_e[2 * t + 1] = b1;  g_route_w[2 * t + 1] = e1 / s;
        atomicAdd(&g_counts[b0], 1);
        atomicAdd(&g_counts[b1], 1);
    }
}

__global__ void scan_kernel() {
    if (threadIdx.x == 0) {
        int o = 0;
        for (int e = 0; e < NE; e++) { g_offsets[e] = o; o += g_counts[e]; }
    }
}

__global__ void scatter_kernel() {
    int i = blockIdx.x * blockDim.x + threadIdx.x;
    if (i >= NROWS) return;
    int e = g_route_e[i];
    int p = atomicAdd(&g_ctr[e], 1);
    int r = g_offsets[e] + p;
    g_perm[r] = i >> 1;
    g_pw[r]   = g_route_w[i];
}

// ---------------------------------------------------------------------------
// shared GEMM geometry: smem row = 40 halves (80 B, 16B aligned), 3 stages
// ---------------------------------------------------------------------------
#define SPAD 40
#define ATILE 10240                 // 128 rows * 80 B
#define STAGE (2 * ATILE)           // A + B
#define GSMEM (3 * STAGE)           // 61440 B dynamic

// ---------------------------------------------------------------------------
// GEMM1: xh[gathered 128, 1024] @ {w1h,w3h}[64,1024]^T -> silu-gate -> g_h
// warps 4(m)x2(n); cp.async 3-stage; ldmatrix frags
// ---------------------------------------------------------------------------
__global__ __launch_bounds__(256, 2) void gemm1_kernel() {
    extern __shared__ char dsm[];
    __shared__ int stok[128];

    int e   = blockIdx.z;
    int cnt = g_counts[e];
    int m0  = blockIdx.x * 128;          // m fastest -> B-slice L2 reuse
    if (m0 >= cnt) return;
    int n0  = blockIdx.y * 64;
    int off = g_offsets[e];

    int tid = threadIdx.x;
    if (tid < 128)
        stok[tid] = (m0 + tid < cnt) ? g_perm[off + m0 + tid] : -1;
    __syncthreads();

    const __half* w1e = g_w1h + (size_t)e * NH * ND;
    const __half* w3e = g_w3h + (size_t)e * NH * ND;

    int r  = tid >> 2;          // 0..63
    int ch = tid & 3;           // 16B chunk
    const __half* ap[2]; int abytes[2];
#pragma unroll
    for (int i = 0; i < 2; i++) {
        int tok = stok[r + 64 * i];
        ap[i]     = (tok >= 0) ? (g_xh + (size_t)tok * ND + ch * 8) : g_xh;
        abytes[i] = (tok >= 0) ? 16 : 0;
    }
    const __half* bp0 = w1e + (size_t)(n0 + r) * ND + ch * 8;
    const __half* bp1 = w3e + (size_t)(n0 + r) * ND + ch * 8;

    uint32_t sbase = smem_u32(dsm);
    uint32_t dA0 = (uint32_t)(r * 80 + ch * 16);
    uint32_t dA1 = (uint32_t)((r + 64) * 80 + ch * 16);

    int lane = tid & 31, wid = tid >> 5;
    int wm = wid >> 1, wn = wid & 1;
    int g = lane >> 2, t = lane & 3;

    uint32_t aOff = (uint32_t)((wm * 32 + (lane & 15)) * 80 + (lane >> 4) * 16);
    uint32_t bOff = (uint32_t)(((lane & 7) + 8 * (lane >> 4)) * 80 + ((lane >> 3) & 1) * 16) + ATILE;
    uint32_t bw   = (uint32_t)(wn * 32) * 80;

    float acc1[2][4][4], acc3[2][4][4];
#pragma unroll
    for (int mi = 0; mi < 2; mi++)
#pragma unroll
        for (int ni = 0; ni < 4; ni++)
#pragma unroll
            for (int q = 0; q < 4; q++) { acc1[mi][ni][q] = 0.f; acc3[mi][ni][q] = 0.f; }

    const int KT = ND / 32;   // 32

    // prefill stages 0,1
#pragma unroll
    for (int p = 0; p < 2; p++) {
        uint32_t st = sbase + p * STAGE;
        int ko = p * 32;
        cpa16(st + dA0, ap[0] + ko, abytes[0]);
        cpa16(st + dA1, ap[1] + ko, abytes[1]);
        cpa16(st + ATILE + dA0, bp0 + ko, 16);
        cpa16(st + ATILE + dA1, bp1 + ko, 16);
        CPA_COMMIT();
    }

    for (int kt = 0; kt < KT; kt++) {
        CPA_WAIT1();
        __syncthreads();
        if (kt + 2 < KT) {
            uint32_t st = sbase + ((kt + 2) % 3) * STAGE;
            int ko = (kt + 2) * 32;
            cpa16(st + dA0, ap[0] + ko, abytes[0]);
            cpa16(st + dA1, ap[1] + ko, abytes[1]);
            cpa16(st + ATILE + dA0, bp0 + ko, 16);
            cpa16(st + ATILE + dA1, bp1 + ko, 16);
        }
        CPA_COMMIT();

        uint32_t st = sbase + (kt % 3) * STAGE;
        uint32_t aAddr = st + aOff;
        uint32_t bAddr = st + bOff + bw;
#pragma unroll
        for (int kc = 0; kc < 2; kc++) {
            uint32_t kb = kc * 32;
            uint32_t af[2][4], bf1[2][4], bf3[2][4];
            ldsm_x4(af[0], aAddr + kb);
            ldsm_x4(af[1], aAddr + kb + 16 * 80);
            ldsm_x4(bf1[0], bAddr + kb);
            ldsm_x4(bf1[1], bAddr + kb + 16 * 80);
            ldsm_x4(bf3[0], bAddr + kb + 64 * 80);
            ldsm_x4(bf3[1], bAddr + kb + 80 * 80);
#pragma unroll
            for (int mi = 0; mi < 2; mi++)
#pragma unroll
                for (int j = 0; j < 4; j++) {
                    mma_f16(acc1[mi][j], af[mi], &bf1[j >> 1][2 * (j & 1)]);
                    mma_f16(acc3[mi][j], af[mi], &bf3[j >> 1][2 * (j & 1)]);
                }
        }
    }

    // epilogue: silu(acc1)*acc3 -> half2 -> g_h
#pragma unroll
    for (int mi = 0; mi < 2; mi++) {
#pragma unroll
        for (int hf = 0; hf < 2; hf++) {
            int mrow = wm * 32 + mi * 16 + g + hf * 8;
            int m = m0 + mrow;
            if (m >= cnt) continue;
            size_t rr = (size_t)(off + m);
#pragma unroll
            for (int ni = 0; ni < 4; ni++) {
                float a0 = acc1[mi][ni][hf * 2 + 0];
                float a1 = acc1[mi][ni][hf * 2 + 1];
                float v0 = (a0 / (1.f + __expf(-a0))) * acc3[mi][ni][hf * 2 + 0];
                float v1 = (a1 / (1.f + __expf(-a1))) * acc3[mi][ni][hf * 2 + 1];
                int col = n0 + wn * 32 + ni * 8 + 2 * t;
                *(__half2*)(g_h + rr * NH + col) = __floats2half2_rn(v0, v1);
            }
        }
    }
}

// ---------------------------------------------------------------------------
// GEMM2: g_h[128, 2816] @ w2h[128, 2816]^T * pw -> atomicAdd out
// warps 2(m)x4(n); cp.async 3-stage; ldmatrix frags
// ---------------------------------------------------------------------------
__global__ __launch_bounds__(256, 2) void gemm2_kernel(float* __restrict__ out) {
    extern __shared__ char dsm[];

    int e   = blockIdx.z;
    int cnt = g_counts[e];
    int m0  = blockIdx.y * 128;
    if (m0 >= cnt) return;
    int n0  = blockIdx.x * 128;          // n fastest -> A-slice L2 reuse
    int off = g_offsets[e];

    int tid = threadIdx.x;
    const __half* w2e = g_w2h + (size_t)e * ND * NH;

    int r  = tid >> 2;
    int ch = tid & 3;
    const __half* ap[2]; int abytes[2];
#pragma unroll
    for (int i = 0; i < 2; i++) {
        bool valid = (m0 + r + 64 * i) < cnt;
        ap[i]     = valid ? (g_h + (size_t)(off + m0 + r + 64 * i) * NH + ch * 8) : g_h;
        abytes[i] = valid ? 16 : 0;
    }
    const __half* bp[2];
#pragma unroll
    for (int i = 0; i < 2; i++)
        bp[i] = w2e + (size_t)(n0 + r + 64 * i) * NH + ch * 8;

    uint32_t sbase = smem_u32(dsm);
    uint32_t dA0 = (uint32_t)(r * 80 + ch * 16);
    uint32_t dA1 = (uint32_t)((r + 64) * 80 + ch * 16);

    int lane = tid & 31, wid = tid >> 5;
    int wm = wid >> 2, wn = wid & 3;
    int g = lane >> 2, t = lane & 3;

    uint32_t aOff = (uint32_t)((wm * 64 + (lane & 15)) * 80 + (lane >> 4) * 16);
    uint32_t bOff = (uint32_t)(((lane & 7) + 8 * (lane >> 4)) * 80 + ((lane >> 3) & 1) * 16) + ATILE;
    uint32_t bw   = (uint32_t)(wn * 32) * 80;

    float acc[4][4][4];
#pragma unroll
    for (int mi = 0; mi < 4; mi++)
#pragma unroll
        for (int ni = 0; ni < 4; ni++)
#pragma unroll
            for (int q = 0; q < 4; q++) acc[mi][ni][q] = 0.f;

    const int KT = NH / 32;   // 88

#pragma unroll
    for (int p = 0; p < 2; p++) {
        uint32_t st = sbase + p * STAGE;
        int ko = p * 32;
        cpa16(st + dA0, ap[0] + ko, abytes[0]);
        cpa16(st + dA1, ap[1] + ko, abytes[1]);
        cpa16(st + ATILE + dA0, bp[0] + ko, 16);
        cpa16(st + ATILE + dA1, bp[1] + ko, 16);
        CPA_COMMIT();
    }

    for (int kt = 0; kt < KT; kt++) {
        CPA_WAIT1();
        __syncthreads();
        if (kt + 2 < KT) {
            uint32_t st = sbase + ((kt + 2) % 3) * STAGE;
            int ko = (kt + 2) * 32;
            cpa16(st + dA0, ap[0] + ko, abytes[0]);
            cpa16(st + dA1, ap[1] + ko, abytes[1]);
            cpa16(st + ATILE + dA0, bp[0] + ko, 16);
            cpa16(st + ATILE + dA1, bp[1] + ko, 16);
        }
        CPA_COMMIT();

        uint32_t st = sbase + (kt % 3) * STAGE;
        uint32_t aAddr = st + aOff;
        uint32_t bAddr = st + bOff + bw;
#pragma unroll
        for (int kc = 0; kc < 2; kc++) {
            uint32_t kb = kc * 32;
            uint32_t af[4][4], bf[2][4];
#pragma unroll
            for (int mi = 0; mi < 4; mi++)
                ldsm_x4(af[mi], aAddr + kb + (uint32_t)(mi * 16) * 80);
            ldsm_x4(bf[0], bAddr + kb);
            ldsm_x4(bf[1], bAddr + kb + 16 * 80);
#pragma unroll
            for (int mi = 0; mi < 4; mi++)
#pragma unroll
                for (int j = 0; j < 4; j++)
                    mma_f16(acc[mi][j], af[mi], &bf[j >> 1][2 * (j & 1)]);
        }
    }

    // epilogue: scale by combine weight, atomicAdd into out
#pragma unroll
    for (int mi = 0; mi < 4; mi++) {
#pragma unroll
        for (int hf = 0; hf < 2; hf++) {
            int mrow = wm * 64 + mi * 16 + g + hf * 8;
            int m = m0 + mrow;
            if (m >= cnt) continue;
            int rr = off + m;
            int tok = g_perm[rr];
            float w = g_pw[rr];
            float* orow = out + (size_t)tok * ND;
#pragma unroll
            for (int ni = 0; ni < 4; ni++) {
                int col = n0 + wn * 32 + ni * 8 + 2 * t;
                atomicAdd(orow + col,     w * acc[mi][ni][hf * 2 + 0]);
                atomicAdd(orow + col + 1, w * acc[mi][ni][hf * 2 + 1]);
            }
        }
    }
}

// ---------------------------------------------------------------------------
extern "C" void kernel_launch(void* const* d_in, const int* in_sizes, int n_in,
                              void* d_out, int out_size) {
    const float* x  = (const float*)d_in[0];
    const float* gw = (const float*)d_in[1];
    const float* w1 = (const float*)d_in[2];
    const float* w2 = (const float*)d_in[3];
    const float* w3 = (const float*)d_in[4];
    float* out = (float*)d_out;

    cudaFuncSetAttribute(gemm1_kernel, cudaFuncAttributeMaxDynamicSharedMemorySize, GSMEM);
    cudaFuncSetAttribute(gemm2_kernel, cudaFuncAttributeMaxDynamicSharedMemorySize, GSMEM);

    dim3 pg((NW4 + 255) / 256, 4);
    prep_kernel<<<pg, 256>>>((const float4*)x, (const float4*)w1,
                             (const float4*)w2, (const float4*)w3, (float4*)out);
    router_kernel<<<NT / 8, 256>>>(x, gw);
    scan_kernel<<<1, 32>>>();
    scatter_kernel<<<(NROWS + 255) / 256, 256>>>();

    dim3 g1(NROWS / 128, NH / 64, NE);   // m fastest; (128, 44, 8)
    gemm1_kernel<<<g1, 256, GSMEM>>>();

    dim3 g2(ND / 128, NROWS / 128, NE);  // n fastest; (8, 128, 8)
    gemm2_kernel<<<g2, 256, GSMEM>>>(out);
}